// round 1
// baseline (speedup 1.0000x reference)
#include <cuda_runtime.h>
#include <math.h>

#define BB 32
#define PP 196
#define EE 2048
#define AA 512
#define DD 512
#define MMM 512
#define VV 10000
#define LLL 20
#define TTT 19
#define KCC 3072   /* M + E + D */
#define G4 2048    /* 4*D */

#define OFF_PRED  0
#define OFF_CAPS  (BB*TTT*VV)              /* 6,080,000 */
#define OFF_ALPHA (OFF_CAPS + BB*LLL)      /* 6,080,640 */
#define OFF_SORT  (OFF_ALPHA + BB*TTT*PP)  /* 6,199,808 */

// -------- scratch (static device allocations; no runtime alloc) --------
__device__ float g_att1[BB*PP*AA];        // 12.8 MB
__device__ float g_wcomb[KCC*G4];         // 25 MB  (W_ih | W_hh, k-major)
__device__ float g_wic[EE*1024];          // 8 MB   (W_init_h | W_init_c, k-major)
__device__ float g_mean[BB*EE];
__device__ float g_h[BB*DD];
__device__ float g_c[BB*DD];
__device__ float g_alpha[BB*PP];
__device__ float g_x[BB*KCC];             // [emb_t | gated awe | h]
__device__ float g_part[12*BB*G4];        // split-K partials (gates / init)
__device__ float g_part2[2*BB*10048];     // split-K partials (vocab proj)
__device__ int   g_sortind[BB];
__device__ int   g_declen[BB];
__device__ int   g_caps[BB*LLL];

__device__ __forceinline__ float sigm(float x) { return 1.0f / (1.0f + expf(-x)); }

// -------- setup: stable argsort desc, gather caps, emit caps/sort_ind --------
__global__ void k_setup(const int* __restrict__ lens, const int* __restrict__ caps_in,
                        float* __restrict__ out) {
    __shared__ int s_len[BB];
    __shared__ int s_si[BB];
    int tid = threadIdx.x;
    if (tid < BB) s_len[tid] = lens[tid];
    __syncthreads();
    if (tid < BB) {
        int li = s_len[tid];
        int r = 0;
        for (int j = 0; j < BB; ++j) {
            int lj = s_len[j];
            if (lj > li || (lj == li && j < tid)) r++;
        }
        s_si[r] = tid;
    }
    __syncthreads();
    if (tid < BB) {
        int si = s_si[tid];
        g_sortind[tid] = si;
        g_declen[tid]  = s_len[si] - 1;
        out[OFF_SORT + tid] = (float)si;
    }
    __syncthreads();
    for (int i = tid; i < BB*LLL; i += blockDim.x) {
        int b = i / LLL, w = i % LLL;
        int cv = caps_in[s_si[b]*LLL + w];
        g_caps[i] = cv;
        out[OFF_CAPS + i] = (float)cv;
    }
}

// -------- one-time: build g_wic = [W_init_h | W_init_c] (already k-major) ----
__global__ void k_buildwic(const float* __restrict__ Wih0, const float* __restrict__ Wic0) {
    int idx = blockIdx.x * blockDim.x + threadIdx.x;   // < 2048*1024
    int k = idx >> 10, j = idx & 1023;
    g_wic[idx] = (j < 512) ? Wih0[k*512 + j] : Wic0[k*512 + (j - 512)];
}

// -------- one-time: transpose W_ih/W_hh into g_wcomb[k][j] ------------------
__global__ void k_transpose(const float* __restrict__ W_ih, const float* __restrict__ W_hh) {
    __shared__ float tile[32][33];
    int jt = blockIdx.x * 32;   // output col (j < 2048)
    int kt = blockIdx.y * 32;   // output row (k < 3072); 2560 % 32 == 0 -> no straddle
    int tx = threadIdx.x, ty = threadIdx.y;
    #pragma unroll
    for (int i = 0; i < 4; ++i) {
        int j = jt + ty + i*8;
        int k = kt + tx;
        float v = (kt < 2560) ? W_ih[j*2560 + k] : W_hh[j*512 + (k - 2560)];
        tile[ty + i*8][tx] = v;
    }
    __syncthreads();
    #pragma unroll
    for (int i = 0; i < 4; ++i) {
        int k = kt + ty + i*8;
        g_wcomb[k*2048 + jt + tx] = tile[tx][ty + i*8];
    }
}

// -------- mean over pixels -> g_mean[b][e] ----------------------------------
__global__ void k_mean(const float* __restrict__ enc) {
    int b = blockIdx.y;
    int j = blockIdx.x * 128 + threadIdx.x;   // < 2048
    int sb = g_sortind[b];
    const float* base = enc + (size_t)sb * PP * EE + j;
    float s = 0.0f;
    #pragma unroll 4
    for (int p = 0; p < PP; ++p) s += base[p * EE];
    g_mean[b*EE + j] = s * (1.0f / 196.0f);
}

// -------- generic skinny split-K GEMM: part[seg][b][j] = sum_k X[b,k]W[k,j] --
// grid.x = N/128 chunks, grid.y = K/256 segments. 128 threads: 2 bgroups x 64 cols.
__global__ void skinnyK(const float* __restrict__ X, int ldx,
                        const float* __restrict__ Wt, int ldw,
                        float* __restrict__ part, int npad, int N) {
    __shared__ __align__(16) float Xs[32][256];
    int tid = threadIdx.x;
    int cg = tid & 63;
    int bg = tid >> 6;
    int j0 = blockIdx.x * 128 + cg;
    int j1 = j0 + 64;
    int kb = blockIdx.y * 256;
    // cooperative load of X tile [32][256] via float4
    #pragma unroll
    for (int i = 0; i < 16; ++i) {
        int f = i * 128 + tid;          // quad index < 2048
        int r = f >> 6;
        int cq = (f & 63) << 2;
        float4 v = *reinterpret_cast<const float4*>(X + r*ldx + kb + cq);
        *reinterpret_cast<float4*>(&Xs[r][cq]) = v;
    }
    __syncthreads();

    bool v0 = (j0 < N), v1 = (j1 < N);
    float acc0[16], acc1[16];
    #pragma unroll
    for (int i = 0; i < 16; ++i) { acc0[i] = 0.0f; acc1[i] = 0.0f; }
    int b0 = bg * 16;
    const float* wp = Wt + (size_t)kb * ldw;
    #pragma unroll 4
    for (int kk = 0; kk < 256; ++kk) {
        float w0 = v0 ? wp[kk*ldw + j0] : 0.0f;
        float w1 = v1 ? wp[kk*ldw + j1] : 0.0f;
        #pragma unroll
        for (int i = 0; i < 16; ++i) {
            float xv = Xs[b0 + i][kk];
            acc0[i] = fmaf(xv, w0, acc0[i]);
            acc1[i] = fmaf(xv, w1, acc1[i]);
        }
    }
    float* pp = part + (size_t)blockIdx.y * 32 * npad;
    #pragma unroll
    for (int i = 0; i < 16; ++i) {
        int row = b0 + i;
        if (v0) pp[row*npad + j0] = acc0[i];
        if (v1) pp[row*npad + j1] = acc1[i];
    }
}

// -------- init epilogue: h0/c0 from 8 partials ------------------------------
__global__ void k_init_fin(const float* __restrict__ b_init_h, const float* __restrict__ b_init_c) {
    int idx = blockIdx.x * blockDim.x + threadIdx.x;  // < 16384
    int b = idx >> 9, d = idx & 511;
    float h = b_init_h[d], c = b_init_c[d];
    #pragma unroll
    for (int s = 0; s < 8; ++s) {
        h += g_part[(s*32 + b)*1024 + d];
        c += g_part[(s*32 + b)*1024 + 512 + d];
    }
    g_h[idx] = h;
    g_c[idx] = c;
}

// -------- att1 precompute: [6272,2048] x [2048,512] tiled SGEMM -------------
__global__ void k_att1(const float* __restrict__ enc, const float* __restrict__ W,
                       const float* __restrict__ bias) {
    __shared__ __align__(16) float As[16][128];
    __shared__ __align__(16) float Bs[16][64];
    int tid = threadIdx.x;
    int tx = tid & 15, ty = tid >> 4;
    int rowBase = blockIdx.x * 128;
    int colBase = blockIdx.y * 64;

    // precompute the two A-row source offsets this thread loads
    int q0 = tid, q1 = tid + 256;
    int r0 = rowBase + (q0 >> 2), r1 = rowBase + (q1 >> 2);
    size_t src0 = ((size_t)g_sortind[r0/PP]*PP + (r0 % PP)) * EE + (q0 & 3)*4;
    size_t src1 = ((size_t)g_sortind[r1/PP]*PP + (r1 % PP)) * EE + (q1 & 3)*4;
    int kq0 = (q0 & 3) * 4, kq1 = (q1 & 3) * 4;
    int rl0 = q0 >> 2, rl1 = q1 >> 2;
    int bj = (tid & 15) * 4, bk = tid >> 4;

    float acc[8][4];
    #pragma unroll
    for (int i = 0; i < 8; ++i)
        #pragma unroll
        for (int j = 0; j < 4; ++j) acc[i][j] = 0.0f;

    for (int kb = 0; kb < EE; kb += 16) {
        float4 a0 = *reinterpret_cast<const float4*>(enc + src0 + kb);
        float4 a1 = *reinterpret_cast<const float4*>(enc + src1 + kb);
        As[kq0+0][rl0] = a0.x; As[kq0+1][rl0] = a0.y; As[kq0+2][rl0] = a0.z; As[kq0+3][rl0] = a0.w;
        As[kq1+0][rl1] = a1.x; As[kq1+1][rl1] = a1.y; As[kq1+2][rl1] = a1.z; As[kq1+3][rl1] = a1.w;
        float4 bv = *reinterpret_cast<const float4*>(W + (size_t)(kb + bk)*AA + colBase + bj);
        *reinterpret_cast<float4*>(&Bs[bk][bj]) = bv;
        __syncthreads();
        #pragma unroll
        for (int k = 0; k < 16; ++k) {
            float4 av0 = *reinterpret_cast<const float4*>(&As[k][ty*8]);
            float4 av1 = *reinterpret_cast<const float4*>(&As[k][ty*8 + 4]);
            float4 bw  = *reinterpret_cast<const float4*>(&Bs[k][tx*4]);
            float am[8] = {av0.x, av0.y, av0.z, av0.w, av1.x, av1.y, av1.z, av1.w};
            float bm[4] = {bw.x, bw.y, bw.z, bw.w};
            #pragma unroll
            for (int i = 0; i < 8; ++i)
                #pragma unroll
                for (int j = 0; j < 4; ++j)
                    acc[i][j] = fmaf(am[i], bm[j], acc[i][j]);
        }
        __syncthreads();
    }
    #pragma unroll
    for (int i = 0; i < 8; ++i) {
        int row = rowBase + ty*8 + i;
        #pragma unroll
        for (int j = 0; j < 4; ++j) {
            int col = colBase + tx*4 + j;
            g_att1[(size_t)row*AA + col] = acc[i][j] + bias[col];
        }
    }
}

// -------- per-step attention: att2, e=relu(att1+att2)@W_full, softmax -------
__global__ void k_attn(const float* __restrict__ W_dec, const float* __restrict__ b_dec,
                       const float* __restrict__ W_full, const float* __restrict__ b_full,
                       float* __restrict__ out, int t) {
    __shared__ float hs[DD];
    __shared__ float att2s[AA];
    __shared__ float wfs[AA];
    __shared__ float es[PP];
    __shared__ float red[256];
    int b = blockIdx.x;
    int tid = threadIdx.x;

    hs[tid] = g_h[b*DD + tid]; hs[tid+256] = g_h[b*DD + tid + 256];
    wfs[tid] = W_full[tid];    wfs[tid+256] = W_full[tid + 256];
    __syncthreads();

    #pragma unroll
    for (int cc = 0; cc < 2; ++cc) {
        int c = tid + cc*256;
        float acc = b_dec[c];
        #pragma unroll 4
        for (int k = 0; k < DD; ++k) acc = fmaf(hs[k], W_dec[k*AA + c], acc);
        att2s[c] = acc;
    }
    __syncthreads();

    int w = tid >> 5, lane = tid & 31;
    float bf = b_full[0];
    for (int p = w; p < PP; p += 8) {
        const float* row = g_att1 + ((size_t)b*PP + p)*AA;
        float part = 0.0f;
        #pragma unroll
        for (int i = 0; i < 16; ++i) {
            int a = lane + i*32;
            float v = row[a] + att2s[a];
            v = fmaxf(v, 0.0f);
            part = fmaf(v, wfs[a], part);
        }
        #pragma unroll
        for (int off = 16; off; off >>= 1) part += __shfl_down_sync(0xffffffffu, part, off);
        if (lane == 0) es[p] = part + bf;
    }
    __syncthreads();

    // softmax over 196
    float v = (tid < PP) ? es[tid] : -1e30f;
    red[tid] = v; __syncthreads();
    for (int s = 128; s > 0; s >>= 1) { if (tid < s) red[tid] = fmaxf(red[tid], red[tid+s]); __syncthreads(); }
    float mx = red[0]; __syncthreads();
    float ex = (tid < PP) ? expf(v - mx) : 0.0f;
    red[tid] = ex; __syncthreads();
    for (int s = 128; s > 0; s >>= 1) { if (tid < s) red[tid] += red[tid+s]; __syncthreads(); }
    float inv = 1.0f / red[0];
    if (tid < PP) {
        float alpha = ex * inv;
        g_alpha[b*PP + tid] = alpha;
        float m = (g_declen[b] > t) ? 1.0f : 0.0f;
        out[OFF_ALPHA + ((size_t)b*TTT + t)*PP + tid] = alpha * m;
    }
}

// -------- per-step staging: g_x = [emb_t | sigmoid(hWfb+b)*awe | h] ---------
__global__ void k_awe_gate(const float* __restrict__ enc, const float* __restrict__ emb,
                           const float* __restrict__ W_fbeta, const float* __restrict__ b_fbeta,
                           int t) {
    __shared__ float al[PP];
    __shared__ float hs[DD];
    int b = blockIdx.y;
    int tid = threadIdx.x;
    for (int i = tid; i < PP; i += 128) al[i] = g_alpha[b*PP + i];
    for (int i = tid; i < DD; i += 128) hs[i] = g_h[b*DD + i];
    __syncthreads();

    int j = blockIdx.x * 128 + tid;   // < 3072
    float outv;
    if (j < MMM) {
        int cap = g_caps[b*LLL + t];
        outv = emb[(size_t)cap*MMM + j];
    } else if (j < MMM + EE) {
        int jE = j - MMM;
        int sb = g_sortind[b];
        const float* eb = enc + (size_t)sb*PP*EE + jE;
        float awe = 0.0f;
        #pragma unroll 4
        for (int p = 0; p < PP; ++p) awe = fmaf(al[p], eb[p*EE], awe);
        float ga = b_fbeta[jE];
        #pragma unroll 4
        for (int k = 0; k < DD; ++k) ga = fmaf(hs[k], W_fbeta[k*EE + jE], ga);
        outv = awe * sigm(ga);
    } else {
        outv = hs[j - (MMM + EE)];
    }
    g_x[b*KCC + j] = outv;
}

// -------- LSTM pointwise + state update (from 12 gate partials) -------------
__global__ void k_lstm(const float* __restrict__ b_ih, const float* __restrict__ b_hh, int t) {
    int idx = blockIdx.x * blockDim.x + threadIdx.x;  // < 16384
    int b = idx >> 9, d = idx & 511;
    float s[4];
    #pragma unroll
    for (int g = 0; g < 4; ++g) {
        float acc = b_ih[g*512 + d] + b_hh[g*512 + d];
        #pragma unroll
        for (int seg = 0; seg < 12; ++seg)
            acc += g_part[((size_t)seg*32 + b)*G4 + g*512 + d];
        s[g] = acc;
    }
    float ig = sigm(s[0]), fg = sigm(s[1]), gg = tanhf(s[2]), og = sigm(s[3]);
    float cn = fg * g_c[idx] + ig * gg;
    float hn = og * tanhf(cn);
    if (g_declen[b] > t) { g_h[idx] = hn; g_c[idx] = cn; }
}

// -------- masked vocab-projection epilogue ----------------------------------
__global__ void k_pred_fin(const float* __restrict__ b_fc, float* __restrict__ out, int t) {
    int j = blockIdx.x * 256 + threadIdx.x;
    int b = blockIdx.y;
    if (j >= VV) return;
    float v = 0.0f;
    if (g_declen[b] > t)
        v = g_part2[(size_t)b*10048 + j] + g_part2[(size_t)(32 + b)*10048 + j] + b_fc[j];
    out[OFF_PRED + ((size_t)b*TTT + t)*VV + j] = v;
}

// ============================================================================
extern "C" void kernel_launch(void* const* d_in, const int* in_sizes, int n_in,
                              void* d_out, int out_size) {
    const float* enc       = (const float*)d_in[0];
    const int*   caps_in   = (const int*)  d_in[1];
    const int*   lens      = (const int*)  d_in[2];
    const float* W_enc_att = (const float*)d_in[3];
    const float* b_enc_att = (const float*)d_in[4];
    const float* W_dec_att = (const float*)d_in[5];
    const float* b_dec_att = (const float*)d_in[6];
    const float* W_full    = (const float*)d_in[7];
    const float* b_full    = (const float*)d_in[8];
    const float* emb       = (const float*)d_in[9];
    const float* W_ih      = (const float*)d_in[10];
    const float* W_hh      = (const float*)d_in[11];
    const float* b_ih      = (const float*)d_in[12];
    const float* b_hh      = (const float*)d_in[13];
    const float* W_init_h  = (const float*)d_in[14];
    const float* b_init_h  = (const float*)d_in[15];
    const float* W_init_c  = (const float*)d_in[16];
    const float* b_init_c  = (const float*)d_in[17];
    const float* W_fbeta   = (const float*)d_in[18];
    const float* b_fbeta   = (const float*)d_in[19];
    const float* W_fc      = (const float*)d_in[20];
    const float* b_fc      = (const float*)d_in[21];
    float* out = (float*)d_out;

    k_setup<<<1, 32>>>(lens, caps_in, out);
    k_buildwic<<<8192, 256>>>(W_init_h, W_init_c);
    k_transpose<<<dim3(64, 96), dim3(32, 8)>>>(W_ih, W_hh);
    k_mean<<<dim3(16, BB), 128>>>(enc);

    // h0/c0: mean @ [W_init_h|W_init_c]  (K=2048 -> 8 segs, N=1024 -> 8 chunks)
    float* d_mean; cudaGetSymbolAddress((void**)&d_mean, g_mean);
    float* d_wic;  cudaGetSymbolAddress((void**)&d_wic,  g_wic);
    float* d_part; cudaGetSymbolAddress((void**)&d_part, g_part);
    float* d_x;    cudaGetSymbolAddress((void**)&d_x,    g_x);
    float* d_wc;   cudaGetSymbolAddress((void**)&d_wc,   g_wcomb);
    float* d_h;    cudaGetSymbolAddress((void**)&d_h,    g_h);
    float* d_p2;   cudaGetSymbolAddress((void**)&d_p2,   g_part2);

    skinnyK<<<dim3(8, 8), 128>>>(d_mean, EE, d_wic, 1024, d_part, 1024, 1024);
    k_init_fin<<<64, 256>>>(b_init_h, b_init_c);

    k_att1<<<dim3(49, 8), 256>>>(enc, W_enc_att, b_enc_att);

    for (int t = 0; t < TTT; ++t) {
        k_attn<<<BB, 256>>>(W_dec_att, b_dec_att, W_full, b_full, out, t);
        k_awe_gate<<<dim3(24, BB), 128>>>(enc, emb, W_fbeta, b_fbeta, t);
        skinnyK<<<dim3(16, 12), 128>>>(d_x, KCC, d_wc, G4, d_part, G4, G4);
        k_lstm<<<64, 256>>>(b_ih, b_hh, t);
        skinnyK<<<dim3(79, 2), 128>>>(d_h, DD, W_fc, VV, d_p2, 10048, VV);
        k_pred_fin<<<dim3(40, BB), 256>>>(b_fc, out, t);
    }
    (void)in_sizes; (void)n_in; (void)out_size;
}

// round 2
// speedup vs baseline: 2.4728x; 2.4728x over previous
#include <cuda_runtime.h>
#include <math.h>

#define BB 32
#define PP 196
#define EE 2048
#define AA 512
#define DD 512
#define MMM 512
#define VV 10000
#define LLL 20
#define TTT 19
#define KCC 3072   /* M + E + D */
#define G4 2048    /* 4*D */
#define NBIG 12560 /* V + E + A */

#define OFF_PRED  0
#define OFF_CAPS  (BB*TTT*VV)
#define OFF_ALPHA (OFF_CAPS + BB*LLL)
#define OFF_SORT  (OFF_ALPHA + BB*TTT*PP)

// -------- scratch --------
__device__ float g_att1[BB*PP*AA];
__device__ float g_wcomb[KCC*G4];         // [W_ih | W_hh] k-major
__device__ float g_wic[EE*1024];          // [W_init_h | W_init_c]
__device__ float g_wbig[DD*NBIG];         // [W_fc | W_fbeta | W_dec_att] k-major
__device__ float g_mean[BB*EE];
__device__ float g_h[BB*DD];
__device__ float g_c[BB*DD];
__device__ float g_alpha[BB*PP];
__device__ float g_x[BB*KCC];
__device__ float g_part[24*BB*G4];        // gates / init partials
__device__ float g_part2[4*BB*NBIG];      // combined (preds|gate|att2) partials
__device__ int   g_sortind[BB];
__device__ int   g_declen[BB];
__device__ int   g_caps[BB*LLL];

__device__ __forceinline__ float sigm(float x) { return 1.0f / (1.0f + expf(-x)); }

// -------- setup --------
__global__ void k_setup(const int* __restrict__ lens, const int* __restrict__ caps_in,
                        float* __restrict__ out) {
    __shared__ int s_len[BB];
    __shared__ int s_si[BB];
    int tid = threadIdx.x;
    if (tid < BB) s_len[tid] = lens[tid];
    __syncthreads();
    if (tid < BB) {
        int li = s_len[tid];
        int r = 0;
        for (int j = 0; j < BB; ++j) {
            int lj = s_len[j];
            if (lj > li || (lj == li && j < tid)) r++;
        }
        s_si[r] = tid;
    }
    __syncthreads();
    if (tid < BB) {
        int si = s_si[tid];
        g_sortind[tid] = si;
        g_declen[tid]  = s_len[si] - 1;
        out[OFF_SORT + tid] = (float)si;
    }
    __syncthreads();
    for (int i = tid; i < BB*LLL; i += blockDim.x) {
        int b = i / LLL, w = i % LLL;
        int cv = caps_in[s_si[b]*LLL + w];
        g_caps[i] = cv;
        out[OFF_CAPS + i] = (float)cv;
    }
}

// -------- one-time weight packing --------
__global__ void k_buildwic(const float* __restrict__ Wih0, const float* __restrict__ Wic0) {
    int idx = blockIdx.x * blockDim.x + threadIdx.x;
    int k = idx >> 10, j = idx & 1023;
    g_wic[idx] = (j < 512) ? Wih0[k*512 + j] : Wic0[k*512 + (j - 512)];
}

__global__ void k_transpose(const float* __restrict__ W_ih, const float* __restrict__ W_hh) {
    __shared__ float tile[32][33];
    int jt = blockIdx.x * 32;
    int kt = blockIdx.y * 32;
    int tx = threadIdx.x, ty = threadIdx.y;
    #pragma unroll
    for (int i = 0; i < 4; ++i) {
        int j = jt + ty + i*8;
        int k = kt + tx;
        float v = (kt < 2560) ? W_ih[j*2560 + k] : W_hh[j*512 + (k - 2560)];
        tile[ty + i*8][tx] = v;
    }
    __syncthreads();
    #pragma unroll
    for (int i = 0; i < 4; ++i) {
        int k = kt + ty + i*8;
        g_wcomb[k*2048 + jt + tx] = tile[tx][ty + i*8];
    }
}

__global__ void k_packbig(const float* __restrict__ W_fc, const float* __restrict__ W_fbeta,
                          const float* __restrict__ W_dec) {
    long long idx = (long long)blockIdx.x * 256 + threadIdx.x;
    if (idx >= (long long)DD * NBIG) return;
    int k = (int)(idx / NBIG), j = (int)(idx % NBIG);
    float v;
    if (j < VV)            v = W_fc[(size_t)k*VV + j];
    else if (j < VV + EE)  v = W_fbeta[(size_t)k*EE + (j - VV)];
    else                   v = W_dec[(size_t)k*AA + (j - VV - EE)];
    g_wbig[idx] = v;
}

// -------- mean over pixels (float4, MLP via unroll) --------
__global__ void k_mean(const float* __restrict__ enc) {
    int b = blockIdx.y;
    int j = (blockIdx.x * 128 + threadIdx.x) * 4;
    int sb = g_sortind[b];
    const float* base = enc + (size_t)sb * PP * EE + j;
    float4 s = make_float4(0.f, 0.f, 0.f, 0.f);
    #pragma unroll 4
    for (int p = 0; p < PP; ++p) {
        float4 v = *reinterpret_cast<const float4*>(base + (size_t)p * EE);
        s.x += v.x; s.y += v.y; s.z += v.z; s.w += v.w;
    }
    const float inv = 1.0f / 196.0f;
    s.x *= inv; s.y *= inv; s.z *= inv; s.w *= inv;
    *reinterpret_cast<float4*>(&g_mean[b*EE + j]) = s;
}

// -------- skinny split-K GEMM v2: float4 LDS, float2 weight loads, dbl-buffer -
// grid.x = ceil(N/128), grid.y = K/128. 128 thr: 2 bgroups(16 rows) x 64 colpairs.
__global__ __launch_bounds__(128, 4)
void skinny2(const float* __restrict__ X, int ldx,
             const float* __restrict__ Wt, int ldw,
             float* __restrict__ part, int npad, int N) {
    __shared__ __align__(16) float Xs[32][128];
    int tid = threadIdx.x;
    int cg = tid & 63, bg = tid >> 6;
    int j0 = blockIdx.x * 128 + cg * 2;
    int kb = blockIdx.y * 128;
    #pragma unroll
    for (int i = 0; i < 8; ++i) {
        int f = i * 128 + tid;
        int r = f >> 5, c4 = (f & 31) << 2;
        *reinterpret_cast<float4*>(&Xs[r][c4]) =
            *reinterpret_cast<const float4*>(X + (size_t)r * ldx + kb + c4);
    }
    __syncthreads();
    bool val = (j0 < N);
    const float* wp = Wt + (size_t)kb * ldw + j0;
    float acc[16][2];
    #pragma unroll
    for (int i = 0; i < 16; ++i) { acc[i][0] = 0.f; acc[i][1] = 0.f; }
    int b0 = bg * 16;
    float2 wbuf[2][4];
    #pragma unroll
    for (int u = 0; u < 4; ++u)
        wbuf[0][u] = val ? *reinterpret_cast<const float2*>(wp + (size_t)u * ldw)
                         : make_float2(0.f, 0.f);
    #pragma unroll
    for (int kk = 0; kk < 128; kk += 4) {
        int cur = (kk >> 2) & 1;
        if (kk + 4 < 128) {
            #pragma unroll
            for (int u = 0; u < 4; ++u)
                wbuf[cur ^ 1][u] = val ? *reinterpret_cast<const float2*>(wp + (size_t)(kk + 4 + u) * ldw)
                                       : make_float2(0.f, 0.f);
        }
        #pragma unroll
        for (int i = 0; i < 16; ++i) {
            float4 xv = *reinterpret_cast<const float4*>(&Xs[b0 + i][kk]);
            acc[i][0] = fmaf(xv.x, wbuf[cur][0].x, acc[i][0]);
            acc[i][1] = fmaf(xv.x, wbuf[cur][0].y, acc[i][1]);
            acc[i][0] = fmaf(xv.y, wbuf[cur][1].x, acc[i][0]);
            acc[i][1] = fmaf(xv.y, wbuf[cur][1].y, acc[i][1]);
            acc[i][0] = fmaf(xv.z, wbuf[cur][2].x, acc[i][0]);
            acc[i][1] = fmaf(xv.z, wbuf[cur][2].y, acc[i][1]);
            acc[i][0] = fmaf(xv.w, wbuf[cur][3].x, acc[i][0]);
            acc[i][1] = fmaf(xv.w, wbuf[cur][3].y, acc[i][1]);
        }
    }
    if (val) {
        float* pp = part + ((size_t)blockIdx.y * 32 + b0) * npad + j0;
        #pragma unroll
        for (int i = 0; i < 16; ++i)
            *reinterpret_cast<float2*>(pp + (size_t)i * npad) = make_float2(acc[i][0], acc[i][1]);
    }
}

// -------- init epilogue: h0/c0 from 16 partials ------------------------------
__global__ void k_init_fin(const float* __restrict__ b_init_h, const float* __restrict__ b_init_c) {
    int idx = blockIdx.x * blockDim.x + threadIdx.x;  // < 16384
    int b = idx >> 9, d = idx & 511;
    float h = b_init_h[d], c = b_init_c[d];
    #pragma unroll
    for (int s = 0; s < 16; ++s) {
        h += g_part[(s*32 + b)*1024 + d];
        c += g_part[(s*32 + b)*1024 + 512 + d];
    }
    g_h[idx] = h;
    g_c[idx] = c;
}

// -------- att1: [6272,2048]x[2048,512], 128x128x16 reg-prefetch SGEMM --------
__global__ __launch_bounds__(256, 2)
void k_att1(const float* __restrict__ enc, const float* __restrict__ W,
            const float* __restrict__ bias) {
    __shared__ __align__(16) float As[16][128];
    __shared__ __align__(16) float Bs[16][128];
    int tid = threadIdx.x;
    int rowBase = blockIdx.x * 128;
    int colBase = blockIdx.y * 128;

    // A loader: row = tid>>1, k-offset (tid&1)*8 .. +7 (two float4)
    int arow = tid >> 1;
    int grow = rowBase + arow;
    int ak = (tid & 1) * 8;
    const float* asrc = enc + ((size_t)g_sortind[grow / PP] * PP + (grow % PP)) * EE + ak;
    // B loader: k = tid>>4, n-offset (tid&15)*8 .. +7
    int bk = tid >> 4;
    int bn = (tid & 15) * 8;
    const float* bsrc = W + (size_t)bk * AA + colBase + bn;

    int m0 = (tid >> 4) * 8;
    int n0 = (tid & 15) * 8;

    float acc[8][8];
    #pragma unroll
    for (int i = 0; i < 8; ++i)
        #pragma unroll
        for (int j = 0; j < 8; ++j) acc[i][j] = 0.f;

    float4 pa0 = *reinterpret_cast<const float4*>(asrc);
    float4 pa1 = *reinterpret_cast<const float4*>(asrc + 4);
    float4 pb0 = *reinterpret_cast<const float4*>(bsrc);
    float4 pb1 = *reinterpret_cast<const float4*>(bsrc + 4);

    for (int kb = 0; kb < EE; kb += 16) {
        As[ak+0][arow] = pa0.x; As[ak+1][arow] = pa0.y;
        As[ak+2][arow] = pa0.z; As[ak+3][arow] = pa0.w;
        As[ak+4][arow] = pa1.x; As[ak+5][arow] = pa1.y;
        As[ak+6][arow] = pa1.z; As[ak+7][arow] = pa1.w;
        *reinterpret_cast<float4*>(&Bs[bk][bn])     = pb0;
        *reinterpret_cast<float4*>(&Bs[bk][bn + 4]) = pb1;
        __syncthreads();
        if (kb + 16 < EE) {
            pa0 = *reinterpret_cast<const float4*>(asrc + kb + 16);
            pa1 = *reinterpret_cast<const float4*>(asrc + kb + 20);
            pb0 = *reinterpret_cast<const float4*>(bsrc + (size_t)(kb + 16) * AA);
            pb1 = *reinterpret_cast<const float4*>(bsrc + (size_t)(kb + 16) * AA + 4);
        }
        #pragma unroll
        for (int k = 0; k < 16; ++k) {
            float4 a0 = *reinterpret_cast<const float4*>(&As[k][m0]);
            float4 a1 = *reinterpret_cast<const float4*>(&As[k][m0 + 4]);
            float4 b0 = *reinterpret_cast<const float4*>(&Bs[k][n0]);
            float4 b1 = *reinterpret_cast<const float4*>(&Bs[k][n0 + 4]);
            float am[8] = {a0.x, a0.y, a0.z, a0.w, a1.x, a1.y, a1.z, a1.w};
            float bm[8] = {b0.x, b0.y, b0.z, b0.w, b1.x, b1.y, b1.z, b1.w};
            #pragma unroll
            for (int i = 0; i < 8; ++i)
                #pragma unroll
                for (int j = 0; j < 8; ++j)
                    acc[i][j] = fmaf(am[i], bm[j], acc[i][j]);
        }
        __syncthreads();
    }
    float4 bb0 = *reinterpret_cast<const float4*>(bias + colBase + n0);
    float4 bb1 = *reinterpret_cast<const float4*>(bias + colBase + n0 + 4);
    #pragma unroll
    for (int i = 0; i < 8; ++i) {
        int row = rowBase + m0 + i;
        float4 o0 = make_float4(acc[i][0] + bb0.x, acc[i][1] + bb0.y,
                                acc[i][2] + bb0.z, acc[i][3] + bb0.w);
        float4 o1 = make_float4(acc[i][4] + bb1.x, acc[i][5] + bb1.y,
                                acc[i][6] + bb1.z, acc[i][7] + bb1.w);
        *reinterpret_cast<float4*>(&g_att1[(size_t)row * AA + colBase + n0])     = o0;
        *reinterpret_cast<float4*>(&g_att1[(size_t)row * AA + colBase + n0 + 4]) = o1;
    }
}

// -------- per-step attention: att2 from part2; e=relu(att1+att2)@W_full; softmax
__global__ void k_attn(const float* __restrict__ b_dec, const float* __restrict__ W_full,
                       const float* __restrict__ b_full, float* __restrict__ out, int t) {
    __shared__ float att2s[AA];
    __shared__ float wfs[AA];
    __shared__ float es[PP];
    __shared__ float red[256];
    int b = blockIdx.x;
    int tid = threadIdx.x;

    #pragma unroll
    for (int cc = 0; cc < 2; ++cc) {
        int c = tid + cc * 256;
        float a2 = b_dec[c];
        #pragma unroll
        for (int s = 0; s < 4; ++s)
            a2 += g_part2[((size_t)s * 32 + b) * NBIG + VV + EE + c];
        att2s[c] = a2;
        wfs[c] = W_full[c];
    }
    __syncthreads();

    int w = tid >> 5, lane = tid & 31;
    float bf = b_full[0];
    for (int p = w; p < PP; p += 8) {
        const float* row = g_att1 + ((size_t)b * PP + p) * AA;
        float part = 0.0f;
        #pragma unroll
        for (int i = 0; i < 16; ++i) {
            int a = lane + i * 32;
            float v = row[a] + att2s[a];
            v = fmaxf(v, 0.0f);
            part = fmaf(v, wfs[a], part);
        }
        #pragma unroll
        for (int off = 16; off; off >>= 1) part += __shfl_down_sync(0xffffffffu, part, off);
        if (lane == 0) es[p] = part + bf;
    }
    __syncthreads();

    float v = (tid < PP) ? es[tid] : -1e30f;
    red[tid] = v; __syncthreads();
    for (int s = 128; s > 0; s >>= 1) { if (tid < s) red[tid] = fmaxf(red[tid], red[tid+s]); __syncthreads(); }
    float mx = red[0]; __syncthreads();
    float ex = (tid < PP) ? expf(v - mx) : 0.0f;
    red[tid] = ex; __syncthreads();
    for (int s = 128; s > 0; s >>= 1) { if (tid < s) red[tid] += red[tid+s]; __syncthreads(); }
    float inv = 1.0f / red[0];
    if (tid < PP) {
        float alpha = ex * inv;
        g_alpha[b*PP + tid] = alpha;
        float m = (g_declen[b] > t) ? 1.0f : 0.0f;
        out[OFF_ALPHA + ((size_t)b*TTT + t)*PP + tid] = alpha * m;
    }
}

// -------- staging: g_x = [emb_t | gate*awe | h]; gate from part2 -------------
__global__ void k_stage(const float* __restrict__ enc, const float* __restrict__ emb,
                        const float* __restrict__ b_fbeta, int t) {
    __shared__ float al[PP];
    int b = blockIdx.y;
    int tid = threadIdx.x;
    for (int i = tid; i < PP; i += 128) al[i] = g_alpha[b*PP + i];
    __syncthreads();

    int j = blockIdx.x * 128 + tid;   // < 3072
    float outv;
    if (j < MMM) {
        int cap = g_caps[b*LLL + t];
        outv = emb[(size_t)cap * MMM + j];
    } else if (j < MMM + EE) {
        int jE = j - MMM;
        int sb = g_sortind[b];
        const float* eb = enc + (size_t)sb * PP * EE + jE;
        float awe = 0.0f;
        #pragma unroll 4
        for (int p = 0; p < PP; ++p) awe = fmaf(al[p], eb[(size_t)p * EE], awe);
        float ga = b_fbeta[jE];
        #pragma unroll
        for (int s = 0; s < 4; ++s)
            ga += g_part2[((size_t)s * 32 + b) * NBIG + VV + jE];
        outv = awe * sigm(ga);
    } else {
        outv = g_h[b*DD + (j - (MMM + EE))];
    }
    g_x[b*KCC + j] = outv;
}

// -------- LSTM pointwise (24 gate partials) ---------------------------------
__global__ void k_lstm(const float* __restrict__ b_ih, const float* __restrict__ b_hh, int t) {
    int idx = blockIdx.x * blockDim.x + threadIdx.x;  // < 16384
    int b = idx >> 9, d = idx & 511;
    float s[4];
    #pragma unroll
    for (int g = 0; g < 4; ++g) {
        float acc = b_ih[g*512 + d] + b_hh[g*512 + d];
        #pragma unroll
        for (int seg = 0; seg < 24; ++seg)
            acc += g_part[((size_t)seg * 32 + b) * G4 + g*512 + d];
        s[g] = acc;
    }
    float ig = sigm(s[0]), fg = sigm(s[1]), gg = tanhf(s[2]), og = sigm(s[3]);
    float cn = fg * g_c[idx] + ig * gg;
    float hn = og * tanhf(cn);
    if (g_declen[b] > t) { g_h[idx] = hn; g_c[idx] = cn; }
}

// -------- masked preds epilogue (from part2 cols [0,V)) ----------------------
__global__ void k_fin(const float* __restrict__ b_fc, float* __restrict__ out, int t) {
    int j = blockIdx.x * 256 + threadIdx.x;
    int b = blockIdx.y;
    if (j >= VV) return;
    float v = 0.0f;
    if (g_declen[b] > t) {
        v = b_fc[j];
        #pragma unroll
        for (int s = 0; s < 4; ++s)
            v += g_part2[((size_t)s * 32 + b) * NBIG + j];
    }
    out[OFF_PRED + ((size_t)b*TTT + t)*VV + j] = v;
}

// ============================================================================
extern "C" void kernel_launch(void* const* d_in, const int* in_sizes, int n_in,
                              void* d_out, int out_size) {
    const float* enc       = (const float*)d_in[0];
    const int*   caps_in   = (const int*)  d_in[1];
    const int*   lens      = (const int*)  d_in[2];
    const float* W_enc_att = (const float*)d_in[3];
    const float* b_enc_att = (const float*)d_in[4];
    const float* W_dec_att = (const float*)d_in[5];
    const float* b_dec_att = (const float*)d_in[6];
    const float* W_full    = (const float*)d_in[7];
    const float* b_full    = (const float*)d_in[8];
    const float* emb       = (const float*)d_in[9];
    const float* W_ih      = (const float*)d_in[10];
    const float* W_hh      = (const float*)d_in[11];
    const float* b_ih      = (const float*)d_in[12];
    const float* b_hh      = (const float*)d_in[13];
    const float* W_init_h  = (const float*)d_in[14];
    const float* b_init_h  = (const float*)d_in[15];
    const float* W_init_c  = (const float*)d_in[16];
    const float* b_init_c  = (const float*)d_in[17];
    const float* W_fbeta   = (const float*)d_in[18];
    const float* b_fbeta   = (const float*)d_in[19];
    const float* W_fc      = (const float*)d_in[20];
    const float* b_fc      = (const float*)d_in[21];
    float* out = (float*)d_out;

    float* d_mean; cudaGetSymbolAddress((void**)&d_mean, g_mean);
    float* d_wic;  cudaGetSymbolAddress((void**)&d_wic,  g_wic);
    float* d_part; cudaGetSymbolAddress((void**)&d_part, g_part);
    float* d_p2;   cudaGetSymbolAddress((void**)&d_p2,   g_part2);
    float* d_x;    cudaGetSymbolAddress((void**)&d_x,    g_x);
    float* d_wc;   cudaGetSymbolAddress((void**)&d_wc,   g_wcomb);
    float* d_wb;   cudaGetSymbolAddress((void**)&d_wb,   g_wbig);
    float* d_h;    cudaGetSymbolAddress((void**)&d_h,    g_h);

    k_setup<<<1, 32>>>(lens, caps_in, out);
    k_buildwic<<<8192, 256>>>(W_init_h, W_init_c);
    k_transpose<<<dim3(64, 96), dim3(32, 8)>>>(W_ih, W_hh);
    k_packbig<<<(DD*NBIG + 255)/256, 256>>>(W_fc, W_fbeta, W_dec_att);
    k_mean<<<dim3(4, BB), 128>>>(enc);

    // h0/c0
    skinny2<<<dim3(8, 16), 128>>>(d_mean, EE, d_wic, 1024, d_part, 1024, 1024);
    k_init_fin<<<64, 256>>>(b_init_h, b_init_c);

    // initial combined (att2_0, gate_0)
    skinny2<<<dim3(99, 4), 128>>>(d_h, DD, d_wb, NBIG, d_p2, NBIG, NBIG);

    k_att1<<<dim3(49, 4), 256>>>(enc, W_enc_att, b_enc_att);

    for (int t = 0; t < TTT; ++t) {
        k_attn<<<BB, 256>>>(b_dec_att, W_full, b_full, out, t);
        k_stage<<<dim3(24, BB), 128>>>(enc, emb, b_fbeta, t);
        skinny2<<<dim3(16, 24), 128>>>(d_x, KCC, d_wc, G4, d_part, G4, G4);
        k_lstm<<<64, 256>>>(b_ih, b_hh, t);
        skinny2<<<dim3(99, 4), 128>>>(d_h, DD, d_wb, NBIG, d_p2, NBIG, NBIG);
        k_fin<<<dim3(40, BB), 256>>>(b_fc, out, t);
    }
    (void)in_sizes; (void)n_in; (void)out_size;
}

// round 3
// speedup vs baseline: 2.7833x; 1.1256x over previous
#include <cuda_runtime.h>
#include <math.h>

#define BB 32
#define PP 196
#define EE 2048
#define AA 512
#define DD 512
#define MMM 512
#define VV 10000
#define LLL 20
#define TTT 19
#define KCC 3072   /* M + E + D */
#define G4 2048    /* 4*D */
#define NBIG 12560 /* V + E + A */

#define OFF_PRED  0
#define OFF_CAPS  (BB*TTT*VV)
#define OFF_ALPHA (OFF_CAPS + BB*LLL)
#define OFF_SORT  (OFF_ALPHA + BB*TTT*PP)

typedef unsigned long long ull;

// -------- scratch --------
__device__ float g_att1[BB*PP*AA];
__device__ float g_wcomb[KCC*G4];         // [W_ih | W_hh] k-pair-interleaved
__device__ float g_wic[EE*1024];          // [W_init_h | W_init_c] k-pair-interleaved
__device__ float g_wbig[DD*NBIG];         // [W_fc | W_fbeta | W_dec_att] k-pair-interleaved
__device__ float g_mean[BB*EE];
__device__ float g_h[BB*DD];
__device__ float g_c[BB*DD];
__device__ float g_alpha[BB*PP];
__device__ float g_x[BB*KCC];
__device__ float g_part[24*BB*G4];        // gates / init partials
__device__ float g_part2[4*BB*NBIG];      // combined (preds|gate|att2) partials
__device__ int   g_sortind[BB];
__device__ int   g_declen[BB];
__device__ int   g_caps[BB*LLL];

__device__ __forceinline__ float sigm(float x) { return 1.0f / (1.0f + expf(-x)); }

__device__ __forceinline__ ull ffma2(ull a, ull b, ull c) {
    ull d;
    asm("fma.rn.f32x2 %0, %1, %2, %3;" : "=l"(d) : "l"(a), "l"(b), "l"(c));
    return d;
}
__device__ __forceinline__ float pairsum(ull v) {
    float2 f = *reinterpret_cast<float2*>(&v);
    return f.x + f.y;
}

// -------- setup --------
__global__ void k_setup(const int* __restrict__ lens, const int* __restrict__ caps_in,
                        float* __restrict__ out) {
    __shared__ int s_len[BB];
    __shared__ int s_si[BB];
    int tid = threadIdx.x;
    if (tid < BB) s_len[tid] = lens[tid];
    __syncthreads();
    if (tid < BB) {
        int li = s_len[tid];
        int r = 0;
        for (int j = 0; j < BB; ++j) {
            int lj = s_len[j];
            if (lj > li || (lj == li && j < tid)) r++;
        }
        s_si[r] = tid;
    }
    __syncthreads();
    if (tid < BB) {
        int si = s_si[tid];
        g_sortind[tid] = si;
        g_declen[tid]  = s_len[si] - 1;
        out[OFF_SORT + tid] = (float)si;
    }
    __syncthreads();
    for (int i = tid; i < BB*LLL; i += blockDim.x) {
        int b = i / LLL, w = i % LLL;
        int cv = caps_in[s_si[b]*LLL + w];
        g_caps[i] = cv;
        out[OFF_CAPS + i] = (float)cv;
    }
}

// -------- one-time: pack all three weight blocks, k-pair-interleaved --------
// element (k, j) stored at base[(k>>1)*2N + j*2 + (k&1)]
__global__ void k_pack(const float* __restrict__ W_ih, const float* __restrict__ W_hh,
                       const float* __restrict__ W_fc, const float* __restrict__ W_fbeta,
                       const float* __restrict__ W_dec,
                       const float* __restrict__ Wih0, const float* __restrict__ Wic0) {
    const long long TA = (long long)KCC * G4;
    const long long TB = (long long)DD * NBIG;
    long long idx = (long long)blockIdx.x * 256 + threadIdx.x;
    if (idx < TA) {
        long long a = idx;
        int kp = (int)(a / (2*G4));
        int rem = (int)(a % (2*G4));
        int j = rem >> 1;
        int k = kp*2 + (rem & 1);
        float v = (k < 2560) ? W_ih[(size_t)j*2560 + k] : W_hh[(size_t)j*512 + (k - 2560)];
        g_wcomb[a] = v;
    } else if (idx < TA + TB) {
        long long b = idx - TA;
        int kp = (int)(b / (2*NBIG));
        int rem = (int)(b % (2*NBIG));
        int j = rem >> 1;
        int k = kp*2 + (rem & 1);
        float v;
        if (j < VV)           v = W_fc[(size_t)k*VV + j];
        else if (j < VV + EE) v = W_fbeta[(size_t)k*EE + (j - VV)];
        else                  v = W_dec[(size_t)k*AA + (j - VV - EE)];
        g_wbig[b] = v;
    } else {
        long long c = idx - TA - TB;
        int kp = (int)(c >> 11);
        int rem = (int)(c & 2047);
        int j = rem >> 1;
        int k = kp*2 + (rem & 1);
        float v = (j < 512) ? Wih0[(size_t)k*512 + j] : Wic0[(size_t)k*512 + (j - 512)];
        g_wic[c] = v;
    }
}

// -------- mean over pixels --------
__global__ void k_mean(const float* __restrict__ enc) {
    int b = blockIdx.y;
    int j = (blockIdx.x * 128 + threadIdx.x) * 4;
    int sb = g_sortind[b];
    const float* base = enc + (size_t)sb * PP * EE + j;
    float4 s = make_float4(0.f, 0.f, 0.f, 0.f);
    #pragma unroll 4
    for (int p = 0; p < PP; ++p) {
        float4 v = *reinterpret_cast<const float4*>(base + (size_t)p * EE);
        s.x += v.x; s.y += v.y; s.z += v.z; s.w += v.w;
    }
    const float inv = 1.0f / 196.0f;
    s.x *= inv; s.y *= inv; s.z *= inv; s.w *= inv;
    *reinterpret_cast<float4*>(&g_mean[b*EE + j]) = s;
}

// -------- skinny split-K GEMM v3: FFMA2 half-sums, depth-2 weight prefetch ---
// Wp is k-pair-interleaved. grid.x = ceil(N/128), grid.y = K/128.
// 128 thr: bg = tid>>6 (16 rows each), cg = tid&63 -> cols (base+cg, base+cg+64).
__global__ __launch_bounds__(128, 4)
void skinny3(const float* __restrict__ X, int ldx,
             const float* __restrict__ Wp, int N2 /* = 2N (row stride in pairs) */,
             float* __restrict__ part, int npad, int N) {
    __shared__ __align__(16) float Xs[32][128];
    int tid = threadIdx.x;
    int cg = tid & 63, bg = tid >> 6;
    int j0 = blockIdx.x * 128 + cg;
    int j1 = j0 + 64;
    int kb = blockIdx.y * 128;
    #pragma unroll
    for (int i = 0; i < 8; ++i) {
        int f = i * 128 + tid;
        int r = f >> 5, c4 = (f & 31) << 2;
        *reinterpret_cast<float4*>(&Xs[r][c4]) =
            *reinterpret_cast<const float4*>(X + (size_t)r * ldx + kb + c4);
    }
    __syncthreads();
    bool v0 = (j0 < N), v1 = (j1 < N);
    int b0 = bg * 16;
    // weight base addresses (in pairs): row kp has N2 floats
    const float* w0p = Wp + (size_t)(kb >> 1) * N2 + j0 * 2;
    const float* w1p = Wp + (size_t)(kb >> 1) * N2 + j1 * 2;

    ull acc0[16], acc1[16];
    #pragma unroll
    for (int i = 0; i < 16; ++i) { acc0[i] = 0ull; acc1[i] = 0ull; }

    // 32 groups of 4k (2 kpairs); prefetch 2 groups ahead, 3 rotating buffers
    ull wq[3][4];
    #pragma unroll
    for (int g = 0; g < 2; ++g) {
        size_t o = (size_t)(g * 2) * N2;
        wq[g][0] = v0 ? *reinterpret_cast<const ull*>(w0p + o)      : 0ull;
        wq[g][1] = v0 ? *reinterpret_cast<const ull*>(w0p + o + N2) : 0ull;
        wq[g][2] = v1 ? *reinterpret_cast<const ull*>(w1p + o)      : 0ull;
        wq[g][3] = v1 ? *reinterpret_cast<const ull*>(w1p + o + N2) : 0ull;
    }
    #pragma unroll
    for (int g = 0; g < 32; ++g) {
        int cur = g % 3;
        if (g + 2 < 32) {
            int nxt = (g + 2) % 3;
            size_t o = (size_t)((g + 2) * 2) * N2;
            wq[nxt][0] = v0 ? *reinterpret_cast<const ull*>(w0p + o)      : 0ull;
            wq[nxt][1] = v0 ? *reinterpret_cast<const ull*>(w0p + o + N2) : 0ull;
            wq[nxt][2] = v1 ? *reinterpret_cast<const ull*>(w1p + o)      : 0ull;
            wq[nxt][3] = v1 ? *reinterpret_cast<const ull*>(w1p + o + N2) : 0ull;
        }
        int kk = g * 4;
        #pragma unroll
        for (int i = 0; i < 16; ++i) {
            ulonglong2 xv = *reinterpret_cast<const ulonglong2*>(&Xs[b0 + i][kk]);
            acc0[i] = ffma2(xv.x, wq[cur][0], acc0[i]);
            acc0[i] = ffma2(xv.y, wq[cur][1], acc0[i]);
            acc1[i] = ffma2(xv.x, wq[cur][2], acc1[i]);
            acc1[i] = ffma2(xv.y, wq[cur][3], acc1[i]);
        }
    }
    float* pp = part + ((size_t)blockIdx.y * 32 + b0) * npad;
    #pragma unroll
    for (int i = 0; i < 16; ++i) {
        if (v0) pp[(size_t)i * npad + j0] = pairsum(acc0[i]);
        if (v1) pp[(size_t)i * npad + j1] = pairsum(acc1[i]);
    }
}

// -------- init epilogue: h0/c0 from 16 partials ------------------------------
__global__ void k_init_fin(const float* __restrict__ b_init_h, const float* __restrict__ b_init_c) {
    int idx = blockIdx.x * blockDim.x + threadIdx.x;  // < 16384
    int b = idx >> 9, d = idx & 511;
    float h = b_init_h[d], c = b_init_c[d];
    #pragma unroll
    for (int s = 0; s < 16; ++s) {
        h += g_part[(s*32 + b)*1024 + d];
        c += g_part[(s*32 + b)*1024 + 512 + d];
    }
    g_h[idx] = h;
    g_c[idx] = c;
}

// -------- att1: [6272,2048]x[2048,512], 128x128x16 reg-prefetch SGEMM --------
__global__ __launch_bounds__(256, 2)
void k_att1(const float* __restrict__ enc, const float* __restrict__ W,
            const float* __restrict__ bias) {
    __shared__ __align__(16) float As[16][128];
    __shared__ __align__(16) float Bs[16][128];
    int tid = threadIdx.x;
    int rowBase = blockIdx.x * 128;
    int colBase = blockIdx.y * 128;

    int arow = tid >> 1;
    int grow = rowBase + arow;
    int ak = (tid & 1) * 8;
    const float* asrc = enc + ((size_t)g_sortind[grow / PP] * PP + (grow % PP)) * EE + ak;
    int bk = tid >> 4;
    int bn = (tid & 15) * 8;
    const float* bsrc = W + (size_t)bk * AA + colBase + bn;

    int m0 = (tid >> 4) * 8;
    int n0 = (tid & 15) * 8;

    float acc[8][8];
    #pragma unroll
    for (int i = 0; i < 8; ++i)
        #pragma unroll
        for (int j = 0; j < 8; ++j) acc[i][j] = 0.f;

    float4 pa0 = *reinterpret_cast<const float4*>(asrc);
    float4 pa1 = *reinterpret_cast<const float4*>(asrc + 4);
    float4 pb0 = *reinterpret_cast<const float4*>(bsrc);
    float4 pb1 = *reinterpret_cast<const float4*>(bsrc + 4);

    for (int kb = 0; kb < EE; kb += 16) {
        As[ak+0][arow] = pa0.x; As[ak+1][arow] = pa0.y;
        As[ak+2][arow] = pa0.z; As[ak+3][arow] = pa0.w;
        As[ak+4][arow] = pa1.x; As[ak+5][arow] = pa1.y;
        As[ak+6][arow] = pa1.z; As[ak+7][arow] = pa1.w;
        *reinterpret_cast<float4*>(&Bs[bk][bn])     = pb0;
        *reinterpret_cast<float4*>(&Bs[bk][bn + 4]) = pb1;
        __syncthreads();
        if (kb + 16 < EE) {
            pa0 = *reinterpret_cast<const float4*>(asrc + kb + 16);
            pa1 = *reinterpret_cast<const float4*>(asrc + kb + 20);
            pb0 = *reinterpret_cast<const float4*>(bsrc + (size_t)(kb + 16) * AA);
            pb1 = *reinterpret_cast<const float4*>(bsrc + (size_t)(kb + 16) * AA + 4);
        }
        #pragma unroll
        for (int k = 0; k < 16; ++k) {
            float4 a0 = *reinterpret_cast<const float4*>(&As[k][m0]);
            float4 a1 = *reinterpret_cast<const float4*>(&As[k][m0 + 4]);
            float4 b0 = *reinterpret_cast<const float4*>(&Bs[k][n0]);
            float4 b1 = *reinterpret_cast<const float4*>(&Bs[k][n0 + 4]);
            float am[8] = {a0.x, a0.y, a0.z, a0.w, a1.x, a1.y, a1.z, a1.w};
            float bm[8] = {b0.x, b0.y, b0.z, b0.w, b1.x, b1.y, b1.z, b1.w};
            #pragma unroll
            for (int i = 0; i < 8; ++i)
                #pragma unroll
                for (int j = 0; j < 8; ++j)
                    acc[i][j] = fmaf(am[i], bm[j], acc[i][j]);
        }
        __syncthreads();
    }
    float4 bb0 = *reinterpret_cast<const float4*>(bias + colBase + n0);
    float4 bb1 = *reinterpret_cast<const float4*>(bias + colBase + n0 + 4);
    #pragma unroll
    for (int i = 0; i < 8; ++i) {
        int row = rowBase + m0 + i;
        float4 o0 = make_float4(acc[i][0] + bb0.x, acc[i][1] + bb0.y,
                                acc[i][2] + bb0.z, acc[i][3] + bb0.w);
        float4 o1 = make_float4(acc[i][4] + bb1.x, acc[i][5] + bb1.y,
                                acc[i][6] + bb1.z, acc[i][7] + bb1.w);
        *reinterpret_cast<float4*>(&g_att1[(size_t)row * AA + colBase + n0])     = o0;
        *reinterpret_cast<float4*>(&g_att1[(size_t)row * AA + colBase + n0 + 4]) = o1;
    }
}

// -------- per-step attention --------
__global__ void k_attn(const float* __restrict__ b_dec, const float* __restrict__ W_full,
                       const float* __restrict__ b_full, float* __restrict__ out, int t) {
    __shared__ float att2s[AA];
    __shared__ float wfs[AA];
    __shared__ float es[PP];
    __shared__ float red[256];
    int b = blockIdx.x;
    int tid = threadIdx.x;

    #pragma unroll
    for (int cc = 0; cc < 2; ++cc) {
        int c = tid + cc * 256;
        float a2 = b_dec[c];
        #pragma unroll
        for (int s = 0; s < 4; ++s)
            a2 += g_part2[((size_t)s * 32 + b) * NBIG + VV + EE + c];
        att2s[c] = a2;
        wfs[c] = W_full[c];
    }
    __syncthreads();

    int w = tid >> 5, lane = tid & 31;
    float bf = b_full[0];
    for (int p = w; p < PP; p += 8) {
        const float* row = g_att1 + ((size_t)b * PP + p) * AA;
        float part = 0.0f;
        #pragma unroll
        for (int i = 0; i < 16; ++i) {
            int a = lane + i * 32;
            float v = row[a] + att2s[a];
            v = fmaxf(v, 0.0f);
            part = fmaf(v, wfs[a], part);
        }
        #pragma unroll
        for (int off = 16; off; off >>= 1) part += __shfl_down_sync(0xffffffffu, part, off);
        if (lane == 0) es[p] = part + bf;
    }
    __syncthreads();

    float v = (tid < PP) ? es[tid] : -1e30f;
    red[tid] = v; __syncthreads();
    for (int s = 128; s > 0; s >>= 1) { if (tid < s) red[tid] = fmaxf(red[tid], red[tid+s]); __syncthreads(); }
    float mx = red[0]; __syncthreads();
    float ex = (tid < PP) ? expf(v - mx) : 0.0f;
    red[tid] = ex; __syncthreads();
    for (int s = 128; s > 0; s >>= 1) { if (tid < s) red[tid] += red[tid+s]; __syncthreads(); }
    float inv = 1.0f / red[0];
    if (tid < PP) {
        float alpha = ex * inv;
        g_alpha[b*PP + tid] = alpha;
        float m = (g_declen[b] > t) ? 1.0f : 0.0f;
        out[OFF_ALPHA + ((size_t)b*TTT + t)*PP + tid] = alpha * m;
    }
}

// -------- staging: g_x = [emb_t | gate*awe | h] --------
__global__ void k_stage(const float* __restrict__ enc, const float* __restrict__ emb,
                        const float* __restrict__ b_fbeta, int t) {
    __shared__ float al[PP];
    int b = blockIdx.y;
    int tid = threadIdx.x;
    for (int i = tid; i < PP; i += 128) al[i] = g_alpha[b*PP + i];
    __syncthreads();

    int j = blockIdx.x * 128 + tid;   // < 3072
    float outv;
    if (j < MMM) {
        int cap = g_caps[b*LLL + t];
        outv = emb[(size_t)cap * MMM + j];
    } else if (j < MMM + EE) {
        int jE = j - MMM;
        int sb = g_sortind[b];
        const float* eb = enc + (size_t)sb * PP * EE + jE;
        float awe0 = 0.f, awe1 = 0.f;
        #pragma unroll 8
        for (int p = 0; p < 192; p += 2) {
            awe0 = fmaf(al[p],     eb[(size_t)p * EE],       awe0);
            awe1 = fmaf(al[p + 1], eb[(size_t)(p + 1) * EE], awe1);
        }
        awe0 = fmaf(al[192], eb[(size_t)192 * EE], awe0);
        awe1 = fmaf(al[193], eb[(size_t)193 * EE], awe1);
        awe0 = fmaf(al[194], eb[(size_t)194 * EE], awe0);
        awe1 = fmaf(al[195], eb[(size_t)195 * EE], awe1);
        float awe = awe0 + awe1;
        float ga = b_fbeta[jE];
        #pragma unroll
        for (int s = 0; s < 4; ++s)
            ga += g_part2[((size_t)s * 32 + b) * NBIG + VV + jE];
        outv = awe * sigm(ga);
    } else {
        outv = g_h[b*DD + (j - (MMM + EE))];
    }
    g_x[b*KCC + j] = outv;
}

// -------- LSTM pointwise (24 gate partials) --------
__global__ void k_lstm(const float* __restrict__ b_ih, const float* __restrict__ b_hh, int t) {
    int idx = blockIdx.x * blockDim.x + threadIdx.x;  // < 16384
    int b = idx >> 9, d = idx & 511;
    float s[4];
    #pragma unroll
    for (int g = 0; g < 4; ++g) {
        float acc = b_ih[g*512 + d] + b_hh[g*512 + d];
        #pragma unroll
        for (int seg = 0; seg < 24; ++seg)
            acc += g_part[((size_t)seg * 32 + b) * G4 + g*512 + d];
        s[g] = acc;
    }
    float ig = sigm(s[0]), fg = sigm(s[1]), gg = tanhf(s[2]), og = sigm(s[3]);
    float cn = fg * g_c[idx] + ig * gg;
    float hn = og * tanhf(cn);
    if (g_declen[b] > t) { g_h[idx] = hn; g_c[idx] = cn; }
}

// -------- masked preds epilogue --------
__global__ void k_fin(const float* __restrict__ b_fc, float* __restrict__ out, int t) {
    int j = blockIdx.x * 256 + threadIdx.x;
    int b = blockIdx.y;
    if (j >= VV) return;
    float v = 0.0f;
    if (g_declen[b] > t) {
        v = b_fc[j];
        #pragma unroll
        for (int s = 0; s < 4; ++s)
            v += g_part2[((size_t)s * 32 + b) * NBIG + j];
    }
    out[OFF_PRED + ((size_t)b*TTT + t)*VV + j] = v;
}

// ============================================================================
extern "C" void kernel_launch(void* const* d_in, const int* in_sizes, int n_in,
                              void* d_out, int out_size) {
    const float* enc       = (const float*)d_in[0];
    const int*   caps_in   = (const int*)  d_in[1];
    const int*   lens      = (const int*)  d_in[2];
    const float* W_enc_att = (const float*)d_in[3];
    const float* b_enc_att = (const float*)d_in[4];
    const float* W_dec_att = (const float*)d_in[5];
    const float* b_dec_att = (const float*)d_in[6];
    const float* W_full    = (const float*)d_in[7];
    const float* b_full    = (const float*)d_in[8];
    const float* emb       = (const float*)d_in[9];
    const float* W_ih      = (const float*)d_in[10];
    const float* W_hh      = (const float*)d_in[11];
    const float* b_ih      = (const float*)d_in[12];
    const float* b_hh      = (const float*)d_in[13];
    const float* W_init_h  = (const float*)d_in[14];
    const float* b_init_h  = (const float*)d_in[15];
    const float* W_init_c  = (const float*)d_in[16];
    const float* b_init_c  = (const float*)d_in[17];
    const float* W_fbeta   = (const float*)d_in[18];
    const float* b_fbeta   = (const float*)d_in[19];
    const float* W_fc      = (const float*)d_in[20];
    const float* b_fc      = (const float*)d_in[21];
    float* out = (float*)d_out;

    float* d_mean; cudaGetSymbolAddress((void**)&d_mean, g_mean);
    float* d_wic;  cudaGetSymbolAddress((void**)&d_wic,  g_wic);
    float* d_part; cudaGetSymbolAddress((void**)&d_part, g_part);
    float* d_p2;   cudaGetSymbolAddress((void**)&d_p2,   g_part2);
    float* d_x;    cudaGetSymbolAddress((void**)&d_x,    g_x);
    float* d_wc;   cudaGetSymbolAddress((void**)&d_wc,   g_wcomb);
    float* d_wb;   cudaGetSymbolAddress((void**)&d_wb,   g_wbig);
    float* d_h;    cudaGetSymbolAddress((void**)&d_h,    g_h);

    k_setup<<<1, 32>>>(lens, caps_in, out);                                  // 1
    k_pack<<<57888, 256>>>(W_ih, W_hh, W_fc, W_fbeta, W_dec_att,
                           W_init_h, W_init_c);                              // 2
    k_mean<<<dim3(4, BB), 128>>>(enc);                                       // 3
    skinny3<<<dim3(8, 16), 128>>>(d_mean, EE, d_wic, 2048, d_part, 1024, 1024); // 4
    k_init_fin<<<64, 256>>>(b_init_h, b_init_c);                             // 5
    skinny3<<<dim3(99, 4), 128>>>(d_h, DD, d_wb, 2*NBIG, d_p2, NBIG, NBIG);  // 6 (profiled)
    k_att1<<<dim3(49, 4), 256>>>(enc, W_enc_att, b_enc_att);                 // 7

    for (int t = 0; t < TTT; ++t) {
        k_attn<<<BB, 256>>>(b_dec_att, W_full, b_full, out, t);
        k_stage<<<dim3(24, BB), 128>>>(enc, emb, b_fbeta, t);
        skinny3<<<dim3(16, 24), 128>>>(d_x, KCC, d_wc, 2*G4, d_part, G4, G4);
        k_lstm<<<64, 256>>>(b_ih, b_hh, t);
        skinny3<<<dim3(99, 4), 128>>>(d_h, DD, d_wb, 2*NBIG, d_p2, NBIG, NBIG);
        k_fin<<<dim3(40, BB), 256>>>(b_fc, out, t);
    }
    (void)in_sizes; (void)n_in; (void)out_size;
}